// round 2
// baseline (speedup 1.0000x reference)
#include <cuda_runtime.h>

// CreatePairsSum: for each batch row b with n = jet_num[b] jets,
// out_sum[b, p, :] = inputs[b, i, :] + inputs[b, j, :] for pair p = (i, j)
// of the C(n,2) combinations (dict_vals[n-2, p]); zero for invalid pairs.
// out_num[b] = C(n,2).
//
// Inputs (metadata order):
//   d_in[0]: inputs   float32 [16384, 10, 64]
//   d_in[1]: dict_vals int32  [9, 45, 2]
//   d_in[2]: jet_num  int32   [16384]
// Output: float32, pairs_sum [16384, 45, 64] then pairs_num [16384, 1].

#define BATCH      16384
#define MAX_JETS   10
#define MAX_PAIRS  45
#define N_FEAT     64
#define F4_PER_ROW (N_FEAT / 4)                 // 16 float4 per jet row
#define IN_F4      (MAX_JETS * F4_PER_ROW)      // 160 float4 per batch row
#define OUT_F4     (MAX_PAIRS * F4_PER_ROW)     // 720 float4 per batch row
#define THREADS    256

__global__ __launch_bounds__(THREADS)
void create_pairs_sum_kernel(const float4* __restrict__ in,     // [BATCH * IN_F4]
                             const int2*   __restrict__ dict,   // [9 * MAX_PAIRS]
                             const int*    __restrict__ jet_num,// [BATCH]
                             float4*       __restrict__ out_sum,// [BATCH * OUT_F4]
                             float*        __restrict__ out_num)// [BATCH]
{
    __shared__ float4 s_row[IN_F4];     // this batch's 10x64 input row
    __shared__ int2   s_pairs[MAX_PAIRS];

    const int b   = blockIdx.x;
    const int tid = threadIdx.x;
    const int n   = jet_num[b];

    // Stage input row into shared memory (160 float4, threads 0..159)
    if (tid < IN_F4) {
        s_row[tid] = in[(long long)b * IN_F4 + tid];
    }
    // Stage dict row for this n (45 int2, threads 160..204)
    if (tid >= IN_F4 && tid < IN_F4 + MAX_PAIRS) {
        s_pairs[tid - IN_F4] = dict[(n - 2) * MAX_PAIRS + (tid - IN_F4)];
    }
    if (tid == 0) {
        out_num[b] = (float)(n * (n - 1) / 2);
    }
    __syncthreads();

    float4* __restrict__ dst = out_sum + (long long)b * OUT_F4;

    // 720 float4 outputs striped over 256 threads: iterations at idx, idx+256, idx+512
    #pragma unroll
    for (int idx = tid; idx < OUT_F4; idx += THREADS) {
        const int p = idx >> 4;         // pair index 0..44
        const int c = idx & 15;         // float4 chunk within feature dim
        const int2 ij = s_pairs[p];
        // For invalid pairs ij = (-1,-1); read row 0 instead and mask to zero.
        const int ri = (ij.x < 0) ? 0 : ij.x;
        const int rj = (ij.y < 0) ? 0 : ij.y;
        const float m = (ij.x < 0) ? 0.f : 1.f;
        const float4 a  = s_row[ri * F4_PER_ROW + c];
        const float4 bq = s_row[rj * F4_PER_ROW + c];
        float4 v;
        v.x = m * (a.x + bq.x);
        v.y = m * (a.y + bq.y);
        v.z = m * (a.z + bq.z);
        v.w = m * (a.w + bq.w);
        dst[idx] = v;
    }
}

extern "C" void kernel_launch(void* const* d_in, const int* in_sizes, int n_in,
                              void* d_out, int out_size)
{
    const float4* in      = (const float4*)d_in[0];
    const int2*   dict    = (const int2*)d_in[1];
    const int*    jet_num = (const int*)d_in[2];

    float* out = (float*)d_out;
    float4* out_sum = (float4*)out;                                   // BATCH*45*64 floats
    float*  out_num = out + (long long)BATCH * MAX_PAIRS * N_FEAT;    // BATCH floats

    create_pairs_sum_kernel<<<BATCH, THREADS>>>(in, dict, jet_num,
                                                out_sum, out_num);
}

// round 5
// speedup vs baseline: 1.0749x; 1.0749x over previous
#include <cuda_runtime.h>

// CreatePairsSum, register-blocked version.
// Thread layout: 256 threads/CTA = 16 batch rows x 16 feature-chunks (float4).
// Each thread loads the 10 jet values of its chunk into registers (compulsory
// read traffic only, coalesced), then writes the 45 pair sums directly.
// Pair index is computed arithmetically from (i, j, n):
//   combinations(range(n), 2) lexicographic:  p = i*n - i(i+1)/2 + (j-i-1),
//   valid iff j < n.  Tail p in [C(n,2), 45) is zero-filled.
//
// Inputs (metadata order):
//   d_in[0]: inputs    float32 [16384, 10, 64]
//   d_in[1]: dict_vals int32   [9, 45, 2]   (unused -- ordering is arithmetic)
//   d_in[2]: jet_num   int32   [16384]
// Output: float32, pairs_sum [16384, 45, 64] then pairs_num [16384, 1].

#define BATCH      16384
#define MAX_JETS   10
#define MAX_PAIRS  45
#define N_FEAT     64
#define F4_PER_ROW (N_FEAT / 4)                 // 16 float4 per jet row
#define IN_F4      (MAX_JETS * F4_PER_ROW)      // 160 float4 per batch row
#define OUT_F4     (MAX_PAIRS * F4_PER_ROW)     // 720 float4 per batch row
#define ROWS_PER_CTA 16
#define THREADS    (ROWS_PER_CTA * F4_PER_ROW)  // 256

__global__ __launch_bounds__(THREADS)
void create_pairs_sum_kernel(const float4* __restrict__ in,      // [BATCH * IN_F4]
                             const int*    __restrict__ jet_num, // [BATCH]
                             float4*       __restrict__ out_sum, // [BATCH * OUT_F4]
                             float*        __restrict__ out_num) // [BATCH]
{
    const int tid = threadIdx.x;
    const int c   = tid & (F4_PER_ROW - 1);          // feature chunk 0..15
    const int r   = tid >> 4;                        // local row 0..15
    const int b   = blockIdx.x * ROWS_PER_CTA + r;   // global batch row

    const int n = __ldg(&jet_num[b]);
    const int T = (n * (n - 1)) >> 1;                // C(n,2)

    if (c == 0) {
        out_num[b] = (float)T;
    }

    // Load all 10 jet values for this (row, chunk) into registers.
    const float4* __restrict__ src = in + (long long)b * IN_F4 + c;
    float4 jet[MAX_JETS];
    #pragma unroll
    for (int i = 0; i < MAX_JETS; i++) {
        jet[i] = __ldg(&src[i * F4_PER_ROW]);
    }

    float4* __restrict__ dst = out_sum + (long long)b * OUT_F4 + c;

    // Emit all valid pairs in combinations(range(n)) lexicographic order.
    #pragma unroll
    for (int i = 0; i < MAX_JETS - 1; i++) {
        // base index for block i: i*n - i(i+1)/2 - (i+1), then + j
        const int base = i * n - ((i * (i + 1)) >> 1) - (i + 1);
        #pragma unroll
        for (int j = i + 1; j < MAX_JETS; j++) {
            if (j < n) {
                const int p = base + j;              // pair index for this n
                float4 v;
                v.x = jet[i].x + jet[j].x;
                v.y = jet[i].y + jet[j].y;
                v.z = jet[i].z + jet[j].z;
                v.w = jet[i].w + jet[j].w;
                dst[p * F4_PER_ROW] = v;
            }
        }
    }

    // Zero-fill invalid tail (output buffer is poisoned, must be written).
    const float4 z = make_float4(0.f, 0.f, 0.f, 0.f);
    for (int p = T; p < MAX_PAIRS; p++) {
        dst[p * F4_PER_ROW] = z;
    }
}

extern "C" void kernel_launch(void* const* d_in, const int* in_sizes, int n_in,
                              void* d_out, int out_size)
{
    const float4* in      = (const float4*)d_in[0];
    const int*    jet_num = (const int*)d_in[2];

    float* out = (float*)d_out;
    float4* out_sum = (float4*)out;                                   // BATCH*45*64 floats
    float*  out_num = out + (long long)BATCH * MAX_PAIRS * N_FEAT;    // BATCH floats

    create_pairs_sum_kernel<<<BATCH / ROWS_PER_CTA, THREADS>>>(in, jet_num,
                                                               out_sum, out_num);
}